// round 4
// baseline (speedup 1.0000x reference)
#include <cuda_runtime.h>
#include <math.h>

#define THREADS 256
#define MAXN 4096
#define NB1 1024        // first-pass bins (top 10 bits of key)
#define SH1 22          // 32 - 10

// Order-preserving float->uint key: monotonic increasing with float value.
__device__ __forceinline__ unsigned f2key(float v) {
    unsigned u = __float_as_uint(v);
    return u ^ (unsigned)(((int)u >> 31) | 0x80000000u);
}
__device__ __forceinline__ float key2f(unsigned key) {
    unsigned u = (key & 0x80000000u) ? (key ^ 0x80000000u) : ~key;
    return __uint_as_float(u);
}

// Warp-collective: find bin containing the krem-th element (DESC = count from
// top bin downward, else from bottom upward). Returns bin index + residual rank.
// Register-light: histogram is re-read from smem by the crossing lane.
template<int NB, bool DESC>
__device__ __forceinline__ void resolve(const unsigned* __restrict__ hist, int krem,
                                        int lane, unsigned &bin, int &krem_out)
{
    constexpr int BPL = NB / 32;
    unsigned s = 0;
    #pragma unroll 8
    for (int j = 0; j < BPL; j++) {
        int b = DESC ? (NB - 1 - (lane * BPL + j)) : (lane * BPL + j);
        s += hist[b];
    }
    unsigned p = s;
    #pragma unroll
    for (int o = 1; o < 32; o <<= 1) {
        unsigned t = __shfl_up_sync(0xFFFFFFFFu, p, o);
        if (lane >= o) p += t;
    }
    unsigned excl = p - s;
    bool cross = (excl < (unsigned)krem) && (p >= (unsigned)krem);
    unsigned m = __ballot_sync(0xFFFFFFFFu, cross);
    int src = __ffs(m) - 1;
    unsigned bsel = 0; int k2 = 0;
    if (lane == src) {
        unsigned cum = excl;
        #pragma unroll 8
        for (int j = 0; j < BPL; j++) {
            int b = DESC ? (NB - 1 - (lane * BPL + j)) : (lane * BPL + j);
            unsigned c = hist[b];
            if (cum + c >= (unsigned)krem) { bsel = (unsigned)b; k2 = krem - (int)cum; break; }
            cum += c;
        }
    }
    bin = __shfl_sync(0xFFFFFFFFu, bsel, src);
    krem_out = __shfl_sync(0xFFFFFFFFu, k2, src);
}

__global__ void __launch_bounds__(THREADS)
wildcat_kernel(const float* __restrict__ x, float* __restrict__ out,
               int n, int kmax, int kmin, float alpha)
{
    __shared__ float          s_x[MAXN];
    __shared__ unsigned short s_cand[MAXN];   // H grows from 0, L from MAXN-1
    __shared__ unsigned       s_hist[NB1];    // pass1: 1024 bins; sub-levels: [0:256)=H, [256:512)=L
    __shared__ unsigned       s_selH, s_selL; // evolving key prefixes
    __shared__ int            s_kremH, s_kremL;
    __shared__ int            s_cntH, s_cntL;
    __shared__ float          s_red[2][THREADS / 32];

    const int tid  = threadIdx.x;
    const int lane = tid & 31;
    const int wid  = tid >> 5;
    const long long row = blockIdx.x;
    const float* __restrict__ xr = x + row * (long long)n;

    // ---- init ----
    #pragma unroll
    for (int b = tid; b < NB1; b += THREADS) s_hist[b] = 0;
    if (tid == 0) { s_cntH = 0; s_cntL = 0; }
    __syncthreads();

    // ================= pass 1: vectorized load + 10-bit histogram =============
    const int n4 = n >> 2;
    const float4* __restrict__ xr4 = (const float4*)xr;
    float4* sx4 = (float4*)s_x;
    const int nv4 = (n4 / THREADS) * THREADS;
    for (int i = tid; i < nv4; i += THREADS) {
        float4 v = xr4[i];
        sx4[i] = v;
        atomicAdd(&s_hist[f2key(v.x) >> SH1], 1u);
        atomicAdd(&s_hist[f2key(v.y) >> SH1], 1u);
        atomicAdd(&s_hist[f2key(v.z) >> SH1], 1u);
        atomicAdd(&s_hist[f2key(v.w) >> SH1], 1u);
    }
    for (int i = nv4 * 4 + tid; i < n; i += THREADS) {   // tail (none for n=4096)
        float v = xr[i];
        s_x[i] = v;
        atomicAdd(&s_hist[f2key(v) >> SH1], 1u);
    }
    __syncthreads();

    // ---- resolve first level (shared histogram, two warps in parallel) ----
    if (wid == 0) {
        unsigned b; int k2;
        resolve<NB1, true>(s_hist, kmax, lane, b, k2);
        if (lane == 0) { s_selH = b; s_kremH = k2; }
    } else if (wid == 1) {
        unsigned b; int k2;
        resolve<NB1, false>(s_hist, kmin, lane, b, k2);
        if (lane == 0) { s_selL = b; s_kremL = k2; }
    }
    __syncthreads();

    const unsigned binH = s_selH;
    const unsigned binL = s_selL;
    const bool sameBin = (binH == binL);

    // ===== pass 2: bulk sums + candidate compaction (no ballots) ===============
    float sumT = 0.0f, sumB = 0.0f;
    for (int i = tid; i < nv4; i += THREADS) {
        float4 v = sx4[i];
        float vv[4] = {v.x, v.y, v.z, v.w};
        #pragma unroll
        for (int j = 0; j < 4; j++) {
            float f = vv[j];
            unsigned key = f2key(f);
            unsigned b = key >> SH1;
            if (b > binH) sumT += f;
            if (b < binL) sumB += f;
            if (b == binH) {
                int p = atomicAdd(&s_cntH, 1);
                s_cand[p] = (unsigned short)(4 * i + j);
            } else if (b == binL) {    // implies !sameBin
                int p = atomicAdd(&s_cntL, 1);
                s_cand[MAXN - 1 - p] = (unsigned short)(4 * i + j);
            }
        }
    }
    for (int i = nv4 * 4 + tid; i < n; i += THREADS) {   // tail
        float f = s_x[i];
        unsigned key = f2key(f);
        unsigned b = key >> SH1;
        if (b > binH) sumT += f;
        if (b < binL) sumB += f;
        if (b == binH) {
            int p = atomicAdd(&s_cntH, 1);
            s_cand[p] = (unsigned short)i;
        } else if (b == binL) {
            int p = atomicAdd(&s_cntL, 1);
            s_cand[MAXN - 1 - p] = (unsigned short)i;
        }
    }
    __syncthreads();

    const int cntH = s_cntH;
    const int cntL = sameBin ? cntH : s_cntL;

    // ===== 3 sub-levels over candidate lists: bits 21..14, 13..6, 5..0 =========
    const int dig_sh[3]  = {14, 6, 0};
    const unsigned dig_mk[3] = {0xFFu, 0xFFu, 0x3Fu};
    const int flt_sh[3]  = {SH1, 14, 6};
    const int dig_w[3]   = {8, 8, 6};

    #pragma unroll 1
    for (int lvl = 0; lvl < 3; lvl++) {
        s_hist[tid] = 0;
        s_hist[tid + 256] = 0;
        __syncthreads();
        const unsigned pH = s_selH;
        const unsigned pL = s_selL;
        const int sh = dig_sh[lvl], fs = flt_sh[lvl];
        const unsigned mk = dig_mk[lvl];

        for (int t = tid; t < cntH; t += THREADS) {
            unsigned key = f2key(s_x[s_cand[t]]);
            if ((key >> fs) == pH) atomicAdd(&s_hist[(key >> sh) & mk], 1u);
        }
        for (int t = tid; t < cntL; t += THREADS) {
            int idx = sameBin ? (int)s_cand[t] : (int)s_cand[MAXN - 1 - t];
            unsigned key = f2key(s_x[idx]);
            if ((key >> fs) == pL) atomicAdd(&s_hist[256 + ((key >> sh) & mk)], 1u);
        }
        __syncthreads();

        if (wid == 0) {
            unsigned b; int k2;
            resolve<256, true>(s_hist, s_kremH, lane, b, k2);
            if (lane == 0) { s_selH = (pH << dig_w[lvl]) | b; s_kremH = k2; }
        } else if (wid == 1) {
            unsigned b; int k2;
            resolve<256, false>(s_hist + 256, s_kremL, lane, b, k2);
            if (lane == 0) { s_selL = (pL << dig_w[lvl]) | b; s_kremL = k2; }
        }
        __syncthreads();
    }

    const unsigned keyH = s_selH;   // full 32-bit key of kth largest
    const unsigned keyL = s_selL;   // full 32-bit key of kth smallest

    // ===== tiny final sweep over candidates (strictly above / below) ==========
    for (int t = tid; t < cntH; t += THREADS) {
        float f = s_x[s_cand[t]];
        if (f2key(f) > keyH) sumT += f;
    }
    for (int t = tid; t < cntL; t += THREADS) {
        int idx = sameBin ? (int)s_cand[t] : (int)s_cand[MAXN - 1 - t];
        float f = s_x[idx];
        if (f2key(f) < keyL) sumB += f;
    }

    #pragma unroll
    for (int o = 16; o > 0; o >>= 1) {
        sumT += __shfl_xor_sync(0xFFFFFFFFu, sumT, o);
        sumB += __shfl_xor_sync(0xFFFFFFFFu, sumB, o);
    }
    if (lane == 0) { s_red[0][wid] = sumT; s_red[1][wid] = sumB; }
    __syncthreads();

    if (tid == 0) {
        float st = 0.0f, sb = 0.0f;
        #pragma unroll
        for (int w = 0; w < THREADS / 32; ++w) { st += s_red[0][w]; sb += s_red[1][w]; }
        st += (float)s_kremH * key2f(keyH);   // exact tie handling
        sb += (float)s_kremL * key2f(keyL);
        out[row] = st / (float)kmax + (alpha / (float)kmin) * sb;
    }
}

extern "C" void kernel_launch(void* const* d_in, const int* in_sizes, int n_in,
                              void* d_out, int out_size)
{
    const float* x = (const float*)d_in[0];
    float* out = (float*)d_out;

    const int rows = out_size;                 // 32*512 = 16384
    const int n = in_sizes[0] / rows;          // 4096
    int kmax = (int)lrintf(0.2f * (float)n);   // int(round(0.2*n)) = 819
    int kmin = (int)lrintf(0.2f * (float)n);
    if (kmax < 1) kmax = 1;
    if (kmin < 1) kmin = 1;

    wildcat_kernel<<<rows, THREADS>>>(x, out, n, kmax, kmin, 0.7f);
}